// round 14
// baseline (speedup 1.0000x reference)
#include <cuda_runtime.h>

// Problem constants
#define IMG_W 512
#define IMG_H 512
#define HW (IMG_W * IMG_H)       // 262144
#define NCH 8
#define CHW (NCH * HW)           // 2097152
#define NB 16

// Tile: 32 wide x 16 tall interior, +1 halo each side
#define TLW 32
#define TLH 16
#define NTHREADS 128             // each thread owns a 4-wide pixel quad
#define NBLK (16 * 32 * 16)      // 8192 blocks

// sp layout: per channel 18 rows x stride-40 words; halo col wlh -> word wlh+3
// so interior quads (wlh = 1+4q) land 16B-aligned.
#define SROW 40
#define SCH2 (SROW * 18)         // 720 words per channel
#define SPN (NCH * SCH2)         // 5760 floats = 22.5 KB

__device__ double g_part[NBLK];
__device__ unsigned int g_count = 0;   // re-armed by last block each call

__global__ __launch_bounds__(NTHREADS, 8)
void bicon_main_kernel(const float* __restrict__ cmap,
                       const float* __restrict__ target,
                       const float* __restrict__ con,
                       float* __restrict__ out)
{
    __shared__ __align__(16) float sp[SPN];   // sigmoid(x), 0 for OOB
    __shared__ double sred[NTHREADS / 32];
    __shared__ double sfin[NTHREADS];
    __shared__ int    s_last;

    const int b   = blockIdx.z;
    const int w0  = blockIdx.x * TLW;
    const int h0  = blockIdx.y * TLH;
    const int tid = threadIdx.x;
    const int q   = tid & 7;      // column quad 0..7  -> wcol = 4q..4q+3
    const int row = tid >> 3;     // 0..15

    const float* cb   = cmap   + (size_t)b * CHW;
    const float* conb = con    + (size_t)b * CHW;
    const float* tb   = target + (size_t)b * HW;

    const int gbase = (h0 + row) * IMG_W + (w0 + 4 * q);

    // ---- halo ring: 100 positions, threads 0..99, scalar clamped loads ----
    if (tid < 100) {
        int hlh, wlh;
        if (tid < 34)      { hlh = 0;        wlh = tid;      }
        else if (tid < 68) { hlh = 17;       wlh = tid - 34; }
        else if (tid < 84) { hlh = tid - 67; wlh = 0;        }  // rows 1..16
        else               { hlh = tid - 83; wlh = 33;       }  // rows 1..16
        const int h = h0 + hlh - 1;
        const int w = w0 + wlh - 1;
        const bool valid = ((unsigned)h < (unsigned)IMG_H) &
                           ((unsigned)w < (unsigned)IMG_W);
        const int hc = min(max(h, 0), IMG_H - 1);
        const int wc = min(max(w, 0), IMG_W - 1);
        const float* __restrict__ src = cb + hc * IMG_W + wc;
        #pragma unroll
        for (int c = 0; c < NCH; c++) {
            const float x = src[c * HW];
            const float p = __fdividef(1.0f, 1.0f + __expf(-x));
            sp[c * SCH2 + hlh * SROW + (wlh + 3)] = valid ? p : 0.0f;
        }
    }

    // ---- interior: sigmoid + conmap BCE (log-batched) + t-bitmask ----
    // Processed in two 4-channel batches to keep register staging small.
    // Per element (clips never bind for finite gaussian x):
    //   contribution = log(1+e^-x) + x*(1-t);  sum of logs -> log of product.
    float acc_c = 0.0f;                 // running  x*(1-t)  part
    float prodS[4] = { 1.0f, 1.0f, 1.0f, 1.0f };   // prod of (1+e^-x) over c
    unsigned tmask = 0;                 // bit (8*j + c) = con_target c, pixel j
    const int srow_base = (row + 1) * SROW + 4 + 4 * q;

    #pragma unroll
    for (int half = 0; half < 2; half++) {
        const int c0 = half * 4;
        float4 xc[4], tc[4];
        #pragma unroll
        for (int c = 0; c < 4; c++)
            xc[c] = *reinterpret_cast<const float4*>(cb + (c0 + c) * HW + gbase);
        #pragma unroll
        for (int c = 0; c < 4; c++)
            tc[c] = *reinterpret_cast<const float4*>(conb + (c0 + c) * HW + gbase);

        #pragma unroll
        for (int c = 0; c < 4; c++) {
            const float xs[4] = { xc[c].x, xc[c].y, xc[c].z, xc[c].w };
            const float ts[4] = { tc[c].x, tc[c].y, tc[c].z, tc[c].w };
            float ps[4];
            #pragma unroll
            for (int j = 0; j < 4; j++) {
                const float x = xs[j];
                const float s = 1.0f + __expf(-x);
                ps[j] = __fdividef(1.0f, s);            // sigmoid
                prodS[j] *= s;
                const bool t1 = (ts[j] > 0.5f);
                acc_c += t1 ? 0.0f : x;                 // x*(1-t), t in {0,1}
                tmask |= (t1 ? 1u : 0u) << (8 * j + c0 + c);
            }
            float4 p4; p4.x = ps[0]; p4.y = ps[1]; p4.z = ps[2]; p4.w = ps[3];
            *reinterpret_cast<float4*>(&sp[(c0 + c) * SCH2 + srow_base]) = p4;
        }
    }
    #pragma unroll
    for (int j = 0; j < 4; j++)
        acc_c += __logf(prodS[j]);                  // Σ_c log(1+e^-x) per pixel
    __syncthreads();

    // ---- Phase 2: stencil vote + bimap (log-batched) + decouple BCE ----
    // vote slot k: own channel k, neighbor channel 7-k, offset (dh[k], dw[k])
    static constexpr int dh[8] = { -1, -1, -1,  0,  0,  1,  1,  1 };
    static constexpr int dw[8] = { -1,  0,  1, -1,  1, -1,  0,  1 };

    float prodA0[4] = { 1.0f, 1.0f, 1.0f, 1.0f };   // sel product, k = 0..3
    float prodA1[4] = { 1.0f, 1.0f, 1.0f, 1.0f };   // sel product, k = 4..7
    float acc_bi = 0.0f;                             // +100 per exact-zero sel
    float asum[4] = { 0.0f, 0.0f, 0.0f, 0.0f };
    float amin[4] = { 2.0f, 2.0f, 2.0f, 2.0f };
    const int cbase4 = srow_base;   // center word (add k*SCH2)

    #pragma unroll
    for (int k = 0; k < 8; k++) {
        const float4 c4 = *reinterpret_cast<const float4*>(&sp[k * SCH2 + cbase4]);
        const int nbase = (7 - k) * SCH2 + (row + 1 + dh[k]) * SROW + 4 + 4 * q;
        float4 n4;
        if (dw[k] == 0) {
            n4 = *reinterpret_cast<const float4*>(&sp[nbase]);
        } else if (dw[k] < 0) {
            const float4 v = *reinterpret_cast<const float4*>(&sp[nbase]);
            const float s0 = sp[nbase - 1];
            n4.x = s0; n4.y = v.x; n4.z = v.y; n4.w = v.z;
        } else {
            const float4 v = *reinterpret_cast<const float4*>(&sp[nbase]);
            const float s3 = sp[nbase + 4];
            n4.x = v.y; n4.y = v.z; n4.z = v.w; n4.w = s3;
        }
        const float av[4] = { c4.x * n4.x, c4.y * n4.y, c4.z * n4.z, c4.w * n4.w };
        #pragma unroll
        for (int j = 0; j < 4; j++) {
            const float a = av[j];
            // t in {0,1}: -(t*clip(log a)+(1-t)*clip(log(1-a))) = -clip(log(t?a:1-a))
            float sel = ((tmask >> (8 * j + k)) & 1u) ? a : (1.0f - a);
            const bool z = (sel == 0.0f);           // only a==0 (OOB) & t==1
            acc_bi += z ? 100.0f : 0.0f;            // clip term, exact
            sel = z ? 1.0f : sel;                   // exclude from product
            if (k < 4) prodA0[j] *= sel; else prodA1[j] *= sel;
            asum[j] += a;
            amin[j]  = fminf(amin[j], a);
        }
    }
    #pragma unroll
    for (int j = 0; j < 4; j++)
        acc_bi -= __logf(prodA0[j]) + __logf(prodA1[j]);

    // target loaded late: single vec load, latency covered by other warps
    const float4 tg4 = *reinterpret_cast<const float4*>(tb + gbase);
    float acc_de = 0.0f;
    const float tgs[4] = { tg4.x, tg4.y, tg4.z, tg4.w };
    #pragma unroll
    for (int j = 0; j < 4; j++) {
        const int st   = __popc((tmask >> (8 * j)) & 0xFFu);
        const bool edge = (st > 0) && (st < 8);
        const float dc   = edge ? (1.0f - amin[j]) : (asum[j] * 0.125f);
        const float dsel = (tgs[j] > 0.5f) ? dc : (1.0f - dc);
        acc_de -= fmaxf(__logf(dsel), -100.0f);     // dsel can be exactly 0
    }

    // ---- Block reduction: warp shuffle -> smem -> per-block double partial ----
    float part = 0.8f * acc_c + acc_de + 0.2f * acc_bi;
    #pragma unroll
    for (int o = 16; o > 0; o >>= 1)
        part += __shfl_xor_sync(0xffffffffu, part, o);
    if ((tid & 31) == 0)
        sred[tid >> 5] = (double)part;
    __syncthreads();

    const int bid = (blockIdx.z * gridDim.y + blockIdx.y) * gridDim.x + blockIdx.x;
    if (tid == 0) {
        double s = 0.0;
        #pragma unroll
        for (int k = 0; k < NTHREADS / 32; k++) s += sred[k];
        g_part[bid] = s;
        __threadfence();
        const unsigned ticket = atomicAdd(&g_count, 1u);
        s_last = (ticket == NBLK - 1) ? 1 : 0;
    }
    __syncthreads();

    // ---- Last block: final deterministic reduction over all partials ----
    if (s_last) {
        __threadfence();
        double a = 0.0;
        #pragma unroll
        for (int k = 0; k < NBLK / NTHREADS; k++)      // 64 each, fixed order
            a += g_part[tid + k * NTHREADS];
        sfin[tid] = a;
        __syncthreads();
        #pragma unroll
        for (int off = NTHREADS / 2; off > 0; off >>= 1) {
            if (tid < off) sfin[tid] += sfin[tid + off];
            __syncthreads();
        }
        if (tid == 0) {
            out[0] = (float)sfin[0];
            g_count = 0;    // re-arm for the next graph replay
        }
    }
}

extern "C" void kernel_launch(void* const* d_in, const int* in_sizes, int n_in,
                              void* d_out, int out_size)
{
    const float* c_map      = (const float*)d_in[0];
    const float* target     = (const float*)d_in[1];
    const float* con_target = (const float*)d_in[2];
    float* out = (float*)d_out;

    dim3 grid(IMG_W / TLW, IMG_H / TLH, NB);  // 16 x 32 x 16 = 8192
    bicon_main_kernel<<<grid, NTHREADS>>>(c_map, target, con_target, out);
}

// round 16
// speedup vs baseline: 1.4812x; 1.4812x over previous
#include <cuda_runtime.h>

// Problem constants
#define IMG_W 512
#define IMG_H 512
#define HW (IMG_W * IMG_H)       // 262144
#define NCH 8
#define CHW (NCH * HW)           // 2097152
#define NB 16

// Tile: 32 wide x 16 tall interior, +1 halo each side
#define TLW 32
#define TLH 16
#define NTHREADS 128             // each thread owns a 4-wide pixel quad
#define NBLK (16 * 32 * 16)      // 8192 blocks

// sp layout: per channel 18 rows x stride-40 words; halo col wlh -> word wlh+3
// so interior quads (wlh = 1+4q) land 16B-aligned.
#define SROW 40
#define SCH2 (SROW * 18)         // 720 words per channel
#define SPN (NCH * SCH2)         // 5760 floats = 22.5 KB

__device__ double g_part[NBLK];
__device__ unsigned int g_count = 0;   // re-armed by last block each call

__global__ __launch_bounds__(NTHREADS, 6)
void bicon_main_kernel(const float* __restrict__ cmap,
                       const float* __restrict__ target,
                       const float* __restrict__ con,
                       float* __restrict__ out)
{
    __shared__ __align__(16) float sp[SPN];   // sigmoid(x), 0 for OOB
    __shared__ double sred[NTHREADS / 32];
    __shared__ double sfin[NTHREADS];
    __shared__ int    s_last;

    const int b   = blockIdx.z;
    const int w0  = blockIdx.x * TLW;
    const int h0  = blockIdx.y * TLH;
    const int tid = threadIdx.x;
    const int q   = tid & 7;      // column quad 0..7  -> wcol = 4q..4q+3
    const int row = tid >> 3;     // 0..15

    const float* cb   = cmap   + (size_t)b * CHW;
    const float* conb = con    + (size_t)b * CHW;
    const float* tb   = target + (size_t)b * HW;

    const int gbase = (h0 + row) * IMG_W + (w0 + 4 * q);

    // ---- halo ring: 100 positions, threads 0..99, scalar clamped loads ----
    if (tid < 100) {
        int hlh, wlh;
        if (tid < 34)      { hlh = 0;        wlh = tid;      }
        else if (tid < 68) { hlh = 17;       wlh = tid - 34; }
        else if (tid < 84) { hlh = tid - 67; wlh = 0;        }  // rows 1..16
        else               { hlh = tid - 83; wlh = 33;       }  // rows 1..16
        const int h = h0 + hlh - 1;
        const int w = w0 + wlh - 1;
        const bool valid = ((unsigned)h < (unsigned)IMG_H) &
                           ((unsigned)w < (unsigned)IMG_W);
        const int hc = min(max(h, 0), IMG_H - 1);
        const int wc = min(max(w, 0), IMG_W - 1);
        const float* __restrict__ src = cb + hc * IMG_W + wc;
        #pragma unroll
        for (int c = 0; c < NCH; c++) {
            const float x = src[c * HW];
            const float p = __fdividef(1.0f, 1.0f + __expf(-x));
            sp[c * SCH2 + hlh * SROW + (wlh + 3)] = valid ? p : 0.0f;
        }
    }

    // ---- Phase 1: cmap only. sigmoid -> smem, accumulate t-independent
    //      conmap part:  sum over c,j of (log(1+e^-x) + x). No con loads. ----
    float acc1 = 0.0f;                              // Σ x  (+ Σ log s at end)
    float prodS[4] = { 1.0f, 1.0f, 1.0f, 1.0f };    // prod of (1+e^-x) over c
    const int srow_base = (row + 1) * SROW + 4 + 4 * q;

    #pragma unroll
    for (int half = 0; half < 2; half++) {
        const int c0 = half * 4;
        float4 xc[4];
        #pragma unroll
        for (int c = 0; c < 4; c++)
            xc[c] = *reinterpret_cast<const float4*>(cb + (c0 + c) * HW + gbase);
        #pragma unroll
        for (int c = 0; c < 4; c++) {
            const float xs[4] = { xc[c].x, xc[c].y, xc[c].z, xc[c].w };
            float ps[4];
            #pragma unroll
            for (int j = 0; j < 4; j++) {
                const float x = xs[j];
                const float s = 1.0f + __expf(-x);
                ps[j] = __fdividef(1.0f, s);        // sigmoid
                prodS[j] *= s;
                acc1 += x;                          // x*(1) part; x*t removed in ph2
            }
            float4 p4; p4.x = ps[0]; p4.y = ps[1]; p4.z = ps[2]; p4.w = ps[3];
            *reinterpret_cast<float4*>(&sp[(c0 + c) * SCH2 + srow_base]) = p4;
        }
    }
    #pragma unroll
    for (int j = 0; j < 4; j++)
        acc1 += __logf(prodS[j]);                   // Σ_c log(1+e^-x) per pixel
    __syncthreads();

    // ---- Phase 2: con + target loads (DRAM busy here too), t-bitmask,
    //      stencil vote + bimap (log-batched) + conmap t-part + decouple ----
    unsigned tmask = 0;                 // bit (8*j + c) = con_target c, pixel j
    #pragma unroll
    for (int half = 0; half < 2; half++) {
        const int c0 = half * 4;
        float4 tc[4];
        #pragma unroll
        for (int c = 0; c < 4; c++)
            tc[c] = *reinterpret_cast<const float4*>(conb + (c0 + c) * HW + gbase);
        #pragma unroll
        for (int c = 0; c < 4; c++) {
            const float ts[4] = { tc[c].x, tc[c].y, tc[c].z, tc[c].w };
            #pragma unroll
            for (int j = 0; j < 4; j++)
                tmask |= (ts[j] > 0.5f ? 1u : 0u) << (8 * j + c0 + c);
        }
    }
    const float4 tg4 = *reinterpret_cast<const float4*>(tb + gbase);

    // vote slot k: own channel k, neighbor channel 7-k, offset (dh[k], dw[k])
    static constexpr int dh[8] = { -1, -1, -1,  0,  0,  1,  1,  1 };
    static constexpr int dw[8] = { -1,  0,  1, -1,  1, -1,  0,  1 };

    float prodA0[4] = { 1.0f, 1.0f, 1.0f, 1.0f };   // bimap sel product, k=0..3
    float prodA1[4] = { 1.0f, 1.0f, 1.0f, 1.0f };   // bimap sel product, k=4..7
    float prodP[4]  = { 1.0f, 1.0f, 1.0f, 1.0f };   // prod of p   where t=1
    float prodQ[4]  = { 1.0f, 1.0f, 1.0f, 1.0f };   // prod of 1-p where t=1
    float acc_bi = 0.0f;                             // +100 per exact-zero sel
    float asum[4] = { 0.0f, 0.0f, 0.0f, 0.0f };
    float amin[4] = { 2.0f, 2.0f, 2.0f, 2.0f };
    const int cbase4 = srow_base;   // center word (add k*SCH2)

    #pragma unroll
    for (int k = 0; k < 8; k++) {
        const float4 c4 = *reinterpret_cast<const float4*>(&sp[k * SCH2 + cbase4]);
        const int nbase = (7 - k) * SCH2 + (row + 1 + dh[k]) * SROW + 4 + 4 * q;
        float4 n4;
        if (dw[k] == 0) {
            n4 = *reinterpret_cast<const float4*>(&sp[nbase]);
        } else if (dw[k] < 0) {
            const float4 v = *reinterpret_cast<const float4*>(&sp[nbase]);
            const float s0 = sp[nbase - 1];
            n4.x = s0; n4.y = v.x; n4.z = v.y; n4.w = v.z;
        } else {
            const float4 v = *reinterpret_cast<const float4*>(&sp[nbase]);
            const float s3 = sp[nbase + 4];
            n4.x = v.y; n4.y = v.z; n4.z = v.w; n4.w = s3;
        }
        const float cv[4] = { c4.x, c4.y, c4.z, c4.w };
        const float nv[4] = { n4.x, n4.y, n4.z, n4.w };
        #pragma unroll
        for (int j = 0; j < 4; j++) {
            const float p = cv[j];
            const float a = p * nv[j];
            const bool bit = (tmask >> (8 * j + k)) & 1u;
            // bimap: t in {0,1} => -clip(log(t ? a : 1-a))
            float sel = bit ? a : (1.0f - a);
            const bool z = (sel == 0.0f);           // only a==0 (OOB) & t==1
            acc_bi += z ? 100.0f : 0.0f;            // clip term, exact
            sel = z ? 1.0f : sel;                   // exclude from product
            if (k < 4) prodA0[j] *= sel; else prodA1[j] *= sel;
            // conmap t-part: x*t = log(p) - log(1-p) summed where t=1
            prodP[j] *= bit ? p : 1.0f;
            prodQ[j] *= bit ? (1.0f - p) : 1.0f;
            asum[j] += a;
            amin[j]  = fminf(amin[j], a);
        }
    }
    float acc_xt = 0.0f;
    #pragma unroll
    for (int j = 0; j < 4; j++) {
        acc_bi -= __logf(prodA0[j]) + __logf(prodA1[j]);
        acc_xt += __logf(prodP[j]) - __logf(prodQ[j]);   // Σ x*t
    }
    const float acc_c = acc1 - acc_xt;   // Σ (log s + x*(1-t))

    float acc_de = 0.0f;
    const float tgs[4] = { tg4.x, tg4.y, tg4.z, tg4.w };
    #pragma unroll
    for (int j = 0; j < 4; j++) {
        const int st   = __popc((tmask >> (8 * j)) & 0xFFu);
        const bool edge = (st > 0) && (st < 8);
        const float dc   = edge ? (1.0f - amin[j]) : (asum[j] * 0.125f);
        const float dsel = (tgs[j] > 0.5f) ? dc : (1.0f - dc);
        acc_de -= fmaxf(__logf(dsel), -100.0f);     // dsel can be exactly 0
    }

    // ---- Block reduction: warp shuffle -> smem -> per-block double partial ----
    float part = 0.8f * acc_c + acc_de + 0.2f * acc_bi;
    #pragma unroll
    for (int o = 16; o > 0; o >>= 1)
        part += __shfl_xor_sync(0xffffffffu, part, o);
    if ((tid & 31) == 0)
        sred[tid >> 5] = (double)part;
    __syncthreads();

    const int bid = (blockIdx.z * gridDim.y + blockIdx.y) * gridDim.x + blockIdx.x;
    if (tid == 0) {
        double s = 0.0;
        #pragma unroll
        for (int k = 0; k < NTHREADS / 32; k++) s += sred[k];
        g_part[bid] = s;
        __threadfence();
        const unsigned ticket = atomicAdd(&g_count, 1u);
        s_last = (ticket == NBLK - 1) ? 1 : 0;
    }
    __syncthreads();

    // ---- Last block: final deterministic reduction over all partials ----
    if (s_last) {
        __threadfence();
        double a = 0.0;
        #pragma unroll
        for (int k = 0; k < NBLK / NTHREADS; k++)      // 64 each, fixed order
            a += g_part[tid + k * NTHREADS];
        sfin[tid] = a;
        __syncthreads();
        #pragma unroll
        for (int off = NTHREADS / 2; off > 0; off >>= 1) {
            if (tid < off) sfin[tid] += sfin[tid + off];
            __syncthreads();
        }
        if (tid == 0) {
            out[0] = (float)sfin[0];
            g_count = 0;    // re-arm for the next graph replay
        }
    }
}

extern "C" void kernel_launch(void* const* d_in, const int* in_sizes, int n_in,
                              void* d_out, int out_size)
{
    const float* c_map      = (const float*)d_in[0];
    const float* target     = (const float*)d_in[1];
    const float* con_target = (const float*)d_in[2];
    float* out = (float*)d_out;

    dim3 grid(IMG_W / TLW, IMG_H / TLH, NB);  // 16 x 32 x 16 = 8192
    bicon_main_kernel<<<grid, NTHREADS>>>(c_map, target, con_target, out);
}